// round 6
// baseline (speedup 1.0000x reference)
#include <cuda_runtime.h>
#include <cstdint>

#define PI_F 3.14159265358979323846f

// gate scratch: [b][ph][pw][e] = [16][16][16][8]
__device__ float g_gate[16 * 16 * 16 * 8];

__device__ __forceinline__ uint64_t pack2(float a) {
    uint64_t r;
    asm("mov.b64 %0, {%1, %1};" : "=l"(r) : "r"(__float_as_uint(a)));
    return r;
}
__device__ __forceinline__ uint64_t fma2(uint64_t a, uint64_t b, uint64_t c) {
    uint64_t d;
    asm("fma.rn.f32x2 %0, %1, %2, %3;" : "=l"(d) : "l"(a), "l"(b), "l"(c));
    return d;
}
__device__ __forceinline__ void unpack2(uint64_t v, float& lo, float& hi) {
    uint32_t l, h;
    asm("mov.b64 {%0, %1}, %2;" : "=r"(l), "=r"(h) : "l"(v));
    lo = __uint_as_float(l);
    hi = __uint_as_float(h);
}

// ---------------------------------------------------------------------------
// Kernel 1: per-patch gating. One block (256 thr) per patch (B*16*16 = 4096).
// gate_in layout (matches reference): feature f = c*64 + py*8 + px,
//   c <  64 : x[b, c, ph*8+py, pw*8+px]
//   c >= 64 : fourier feat (constant over py,px):
//             cc = c-64; grp = cc/8 in {sin(fy), cos(fy), sin(fx), cos(fx)}; k = cc%8
// ---------------------------------------------------------------------------
__global__ void gate_kernel(const float* __restrict__ x,
                            const float* __restrict__ gate_w,
                            const float* __restrict__ gate_b) {
    const int blk = blockIdx.x;          // 0..4095
    const int b = blk >> 8;
    const int ph = (blk >> 4) & 15;
    const int pw = blk & 15;
    const int tid = threadIdx.x;

    float part[8];
#pragma unroll
    for (int e = 0; e < 8; e++) part[e] = 0.f;

    const float* xb = x + ((long)b * 64 * 128 + ph * 8) * 128 + pw * 8;

    for (int f = tid; f < 6144; f += 256) {
        int c = f >> 6;
        int r = f & 63;
        float v;
        if (c < 64) {
            int py = r >> 3, px = r & 7;
            v = xb[(c * 128 + py) * 128 + px];
        } else {
            int cc = c - 64;
            int grp = cc >> 3, k = cc & 7;
            float coord = (grp < 2) ? (ph + 0.5f) * (1.f / 16.f)
                                    : (pw + 0.5f) * (1.f / 16.f);
            float ang = coord * ((float)(1 << k) * PI_F);
            v = (grp & 1) ? cosf(ang) : sinf(ang);
        }
#pragma unroll
        for (int e = 0; e < 8; e++) part[e] += v * gate_w[e * 6144 + f];
    }

    // warp reduce
#pragma unroll
    for (int off = 16; off; off >>= 1) {
#pragma unroll
        for (int e = 0; e < 8; e++)
            part[e] += __shfl_down_sync(0xffffffffu, part[e], off);
    }

    __shared__ float s_red[8][8];
    __shared__ float s_logit[8];
    const int warp = tid >> 5, lane = tid & 31;
    if (lane == 0) {
#pragma unroll
        for (int e = 0; e < 8; e++) s_red[warp][e] = part[e];
    }
    __syncthreads();
    if (tid < 8) {
        float s = gate_b[tid];
#pragma unroll
        for (int w = 0; w < 8; w++) s += s_red[w][tid];
        s_logit[tid] = s;
    }
    __syncthreads();
    if (tid < 8) {
        float m = s_logit[0];
#pragma unroll
        for (int e = 1; e < 8; e++) m = fmaxf(m, s_logit[e]);
        float den = 0.f;
#pragma unroll
        for (int e = 0; e < 8; e++) den += expf(s_logit[e] - m);
        g_gate[blk * 8 + tid] = expf(s_logit[tid] - m) / den;
    }
}

// ---------------------------------------------------------------------------
// Kernel 2: fused 8-expert conv3x3 + bias + relu + gated combine.
// Block: batch b, 16x16 pixel tile, 4 base output channels x all 8 experts
// (M = 32 conv channels). Thread: 8 experts (one base oc) x 4 pixels (one row
// quad) = 32 fp32 accumulators as 16 f32x2 pairs (pair = 2 adjacent experts).
// K (64 input channels) chunked by 16 through SMEM. Epilogue combines experts
// in-register -> each output element stored exactly once (no atomics).
// ---------------------------------------------------------------------------
__global__ void __launch_bounds__(256, 2)
conv_kernel(const float* __restrict__ x,
            const float* __restrict__ ew,   // [8][64][64][3][3]
            const float* __restrict__ eb,   // [8][64]
            float* __restrict__ out) {
    __shared__ __align__(16) float in_s[16 * 324];   // [cl][18*18]
    __shared__ __align__(16) float w_s[16 * 9 * 32]; // [cl][tap][m], m = bl*8 + e
    __shared__ float g_s[4][8];                      // [patch-in-tile][e]

    const int tid = threadIdx.x;
    const int tileid = blockIdx.x;       // 0..63
    const int tx = tileid & 7, ty = tileid >> 3;
    const int grp = blockIdx.y;          // base channels grp*4 .. grp*4+3
    const int b = blockIdx.z;

    if (tid < 32) {
        int pp = tid >> 3, e = tid & 7;
        int ph = ty * 2 + (pp >> 1), pw = tx * 2 + (pp & 1);
        g_s[pp][e] = g_gate[((b * 16 + ph) * 16 + pw) * 8 + e];
    }

    const int bl = tid >> 6;   // 0..3 : base-channel within group
    const int gp = tid & 63;
    const int r = gp >> 2;     // pixel row 0..15
    const int q = gp & 3;      // col quad: cols 4q..4q+3

    const int y0 = ty * 16, x0 = tx * 16;
    const int bc = grp * 4 + bl;

    uint64_t acc[4][4];        // [pixel][expert-pair]
#pragma unroll
    for (int p = 0; p < 4; p++)
#pragma unroll
        for (int ep = 0; ep < 4; ep++) acc[p][ep] = 0ull;

    const float* xb = x + (long)b * 64 * 128 * 128;

    for (int c0 = 0; c0 < 64; c0 += 16) {
        // input tile: 16 channels x 18x18 (halo, zero-padded)
        for (int idx = tid; idx < 16 * 324; idx += 256) {
            int c = idx / 324;
            int rem = idx - c * 324;
            int iy = rem / 18;
            int ix = rem - iy * 18;
            int gy = y0 + iy - 1, gx = x0 + ix - 1;
            float v = 0.f;
            if ((unsigned)gy < 128u && (unsigned)gx < 128u)
                v = xb[((c0 + c) * 128 + gy) * 128 + gx];
            in_s[idx] = v;
        }
        // weights: w_s[cl][tap][m], m = blw*8 + e
        for (int idx = tid; idx < 16 * 9 * 32; idx += 256) {
            int cl = idx / 288;
            int rem = idx - cl * 288;
            int tap = rem >> 5;
            int m = rem & 31;
            int blw = m >> 3, e = m & 7;
            w_s[idx] = ew[((e * 64 + grp * 4 + blw) * 64 + c0 + cl) * 9 + tap];
        }
        __syncthreads();

        for (int cl = 0; cl < 16; cl++) {
            const float* base = in_s + cl * 324 + r * 18 + 4 * q;
            // activation window 3 rows x 6 cols, packed {a,a} once, reused
            // across the 9 taps
            uint64_t ap[3][6];
#pragma unroll
            for (int dy = 0; dy < 3; dy++)
#pragma unroll
                for (int j = 0; j < 6; j++)
                    ap[dy][j] = pack2(base[dy * 18 + j]);

            const uint64_t* wrow =
                reinterpret_cast<const uint64_t*>(w_s + cl * 288) + bl * 4;
#pragma unroll
            for (int dy = 0; dy < 3; dy++) {
#pragma unroll
                for (int dx = 0; dx < 3; dx++) {
                    const uint64_t* wp = wrow + (dy * 3 + dx) * 16;
                    uint64_t w0 = wp[0], w1 = wp[1], w2 = wp[2], w3 = wp[3];
#pragma unroll
                    for (int p = 0; p < 4; p++) {
                        uint64_t a = ap[dy][dx + p];
                        acc[p][0] = fma2(w0, a, acc[p][0]);
                        acc[p][1] = fma2(w1, a, acc[p][1]);
                        acc[p][2] = fma2(w2, a, acc[p][2]);
                        acc[p][3] = fma2(w3, a, acc[p][3]);
                    }
                }
            }
        }
        __syncthreads();
    }

    // epilogue: bias + relu + gated combine over 8 experts, single store
    const int pp = ((r >> 3) << 1) + (q >> 1);
    float gv[8], bias[8];
#pragma unroll
    for (int e = 0; e < 8; e++) {
        gv[e] = g_s[pp][e];
        bias[e] = eb[e * 64 + bc];
    }

    float4 o;
    float* op = &o.x;
#pragma unroll
    for (int p = 0; p < 4; p++) {
        float s = 0.f;
#pragma unroll
        for (int ep = 0; ep < 4; ep++) {
            float ylo, yhi;
            unpack2(acc[p][ep], ylo, yhi);
            int e0 = 2 * ep, e1 = 2 * ep + 1;
            s += gv[e0] * fmaxf(ylo + bias[e0], 0.f);
            s += gv[e1] * fmaxf(yhi + bias[e1], 0.f);
        }
        op[p] = s;
    }
    float4* outp = reinterpret_cast<float4*>(
        out + (((long)(b * 64 + bc) * 128 + y0 + r) * 128 + x0 + 4 * q));
    *outp = o;
}

extern "C" void kernel_launch(void* const* d_in, const int* in_sizes, int n_in,
                              void* d_out, int out_size) {
    const float* x  = (const float*)d_in[0];   // [16,64,128,128]
    const float* ew = (const float*)d_in[1];   // [8,64,64,3,3]
    const float* eb = (const float*)d_in[2];   // [8,64]
    const float* gw = (const float*)d_in[3];   // [8,6144]
    const float* gb = (const float*)d_in[4];   // [8]
    float* out = (float*)d_out;                // [16,64,128,128]

    gate_kernel<<<4096, 256>>>(x, gw, gb);

    dim3 grid(64, 16, 16);  // (spatial tile, oc group, batch)
    conv_kernel<<<grid, 256>>>(x, ew, eb, out);
}

// round 7
// speedup vs baseline: 1.1428x; 1.1428x over previous
#include <cuda_runtime.h>
#include <cstdint>

#define PI_F 3.14159265358979323846f

// gate scratch: [b][ph][pw][e] = [16][16][16][8]
__device__ float g_gate[16 * 16 * 16 * 8];

__device__ __forceinline__ uint64_t pack2(float a) {
    uint64_t r;
    asm("mov.b64 %0, {%1, %1};" : "=l"(r) : "r"(__float_as_uint(a)));
    return r;
}
__device__ __forceinline__ uint64_t fma2(uint64_t a, uint64_t b, uint64_t c) {
    uint64_t d;
    asm("fma.rn.f32x2 %0, %1, %2, %3;" : "=l"(d) : "l"(a), "l"(b), "l"(c));
    return d;
}
__device__ __forceinline__ void unpack2(uint64_t v, float& lo, float& hi) {
    uint32_t l, h;
    asm("mov.b64 {%0, %1}, %2;" : "=r"(l), "=r"(h) : "l"(v));
    lo = __uint_as_float(l);
    hi = __uint_as_float(h);
}

// ---------------------------------------------------------------------------
// Kernel 1: per-patch gating. One block (256 thr) per patch (B*16*16 = 4096).
// ---------------------------------------------------------------------------
__global__ void gate_kernel(const float* __restrict__ x,
                            const float* __restrict__ gate_w,
                            const float* __restrict__ gate_b) {
    const int blk = blockIdx.x;          // 0..4095
    const int b = blk >> 8;
    const int ph = (blk >> 4) & 15;
    const int pw = blk & 15;
    const int tid = threadIdx.x;

    float part[8];
#pragma unroll
    for (int e = 0; e < 8; e++) part[e] = 0.f;

    const float* xb = x + ((long)b * 64 * 128 + ph * 8) * 128 + pw * 8;

    for (int f = tid; f < 6144; f += 256) {
        int c = f >> 6;
        int r = f & 63;
        float v;
        if (c < 64) {
            int py = r >> 3, px = r & 7;
            v = xb[(c * 128 + py) * 128 + px];
        } else {
            int cc = c - 64;
            int grp = cc >> 3, k = cc & 7;
            float coord = (grp < 2) ? (ph + 0.5f) * (1.f / 16.f)
                                    : (pw + 0.5f) * (1.f / 16.f);
            float ang = coord * ((float)(1 << k) * PI_F);
            v = (grp & 1) ? cosf(ang) : sinf(ang);
        }
#pragma unroll
        for (int e = 0; e < 8; e++) part[e] += v * gate_w[e * 6144 + f];
    }

#pragma unroll
    for (int off = 16; off; off >>= 1) {
#pragma unroll
        for (int e = 0; e < 8; e++)
            part[e] += __shfl_down_sync(0xffffffffu, part[e], off);
    }

    __shared__ float s_red[8][8];
    __shared__ float s_logit[8];
    const int warp = tid >> 5, lane = tid & 31;
    if (lane == 0) {
#pragma unroll
        for (int e = 0; e < 8; e++) s_red[warp][e] = part[e];
    }
    __syncthreads();
    if (tid < 8) {
        float s = gate_b[tid];
#pragma unroll
        for (int w = 0; w < 8; w++) s += s_red[w][tid];
        s_logit[tid] = s;
    }
    __syncthreads();
    if (tid < 8) {
        float m = s_logit[0];
#pragma unroll
        for (int e = 1; e < 8; e++) m = fmaxf(m, s_logit[e]);
        float den = 0.f;
#pragma unroll
        for (int e = 0; e < 8; e++) den += expf(s_logit[e] - m);
        g_gate[blk * 8 + tid] = expf(s_logit[tid] - m) / den;
    }
}

// ---------------------------------------------------------------------------
// Kernel 2: fused 8-expert conv3x3 + bias + relu + gated combine.
// Block: batch b, 16x16 pixel tile, 8 base output channels x 8 experts
// (M = 64 conv channels). 256 threads: warp = base channel bl (weights are
// warp-uniform -> LDS.128 broadcast), lane -> (row r = lane>>1, half q =
// lane&1). Thread tile: 8 pixels (row r, cols 8q..8q+7) x 8 experts =
// 64 fp32 accs as 32 f32x2 pairs (pair = 2 adjacent experts).
// K chunked by 8 channels through static SMEM. Epilogue combines experts
// in-register -> each output element stored exactly once.
// ---------------------------------------------------------------------------
__global__ void __launch_bounds__(256, 2)
conv_kernel(const float* __restrict__ x,
            const float* __restrict__ ew,   // [8][64][64][3][3]
            const float* __restrict__ eb,   // [8][64]
            float* __restrict__ out) {
    __shared__ __align__(16) float in_s[8 * 324];       // [cl][18*18]
    __shared__ __align__(16) float w_s[8 * 9 * 64];     // [cl][tap][bl*8+e]
    __shared__ float g_s[4][8];                         // [patch-in-tile][e]

    const int tid = threadIdx.x;
    const int tileid = blockIdx.x;       // 0..63
    const int tx = tileid & 7, ty = tileid >> 3;
    const int grp = blockIdx.y;          // base channels grp*8 .. grp*8+7
    const int b = blockIdx.z;

    if (tid < 32) {
        int pp = tid >> 3, e = tid & 7;
        int ph = ty * 2 + (pp >> 1), pw = tx * 2 + (pp & 1);
        g_s[pp][e] = g_gate[((b * 16 + ph) * 16 + pw) * 8 + e];
    }

    const int bl = tid >> 5;             // 0..7 : base channel (== warp id)
    const int lane = tid & 31;
    const int r = lane >> 1;             // pixel row 0..15
    const int q = lane & 1;              // half: cols 8q..8q+7

    const int y0 = ty * 16, x0 = tx * 16;
    const int bc = grp * 8 + bl;

    uint64_t acc[8][4];                  // [pixel][expert-pair]
#pragma unroll
    for (int p = 0; p < 8; p++)
#pragma unroll
        for (int ep = 0; ep < 4; ep++) acc[p][ep] = 0ull;

    const float* xb = x + (long)b * 64 * 128 * 128;

    for (int c0 = 0; c0 < 64; c0 += 8) {
        // input tile: 8 channels x 18x18 (halo, zero-padded)
        for (int idx = tid; idx < 8 * 324; idx += 256) {
            int c = idx / 324;
            int rem = idx - c * 324;
            int iy = rem / 18;
            int ix = rem - iy * 18;
            int gy = y0 + iy - 1, gx = x0 + ix - 1;
            float v = 0.f;
            if ((unsigned)gy < 128u && (unsigned)gx < 128u)
                v = xb[((c0 + c) * 128 + gy) * 128 + gx];
            in_s[idx] = v;
        }
        // weights: w_s[cl][tap][m], m = blw*8 + e
        for (int idx = tid; idx < 8 * 9 * 64; idx += 256) {
            int cl = idx / 576;
            int rem = idx - cl * 576;
            int tap = rem >> 6;
            int m = rem & 63;
            int blw = m >> 3, e = m & 7;
            w_s[idx] = ew[((e * 64 + grp * 8 + blw) * 64 + c0 + cl) * 9 + tap];
        }
        __syncthreads();

#pragma unroll 1
        for (int cl = 0; cl < 8; cl++) {
            const float2* abase = reinterpret_cast<const float2*>(
                in_s + cl * 324 + r * 18 + q * 8);
            const float* wbase = w_s + cl * 576 + bl * 8;
#pragma unroll
            for (int dy = 0; dy < 3; dy++) {
                float2 v0 = abase[dy * 9 + 0];
                float2 v1 = abase[dy * 9 + 1];
                float2 v2 = abase[dy * 9 + 2];
                float2 v3 = abase[dy * 9 + 3];
                float2 v4 = abase[dy * 9 + 4];
                uint64_t ap[10];
                ap[0] = pack2(v0.x); ap[1] = pack2(v0.y);
                ap[2] = pack2(v1.x); ap[3] = pack2(v1.y);
                ap[4] = pack2(v2.x); ap[5] = pack2(v2.y);
                ap[6] = pack2(v3.x); ap[7] = pack2(v3.y);
                ap[8] = pack2(v4.x); ap[9] = pack2(v4.y);
#pragma unroll
                for (int dx = 0; dx < 3; dx++) {
                    const ulonglong2* wq =
                        reinterpret_cast<const ulonglong2*>(
                            wbase + (dy * 3 + dx) * 64);
                    ulonglong2 wab = wq[0];   // expert pairs 0,1 (LDS.128)
                    ulonglong2 wcd = wq[1];   // expert pairs 2,3 (LDS.128)
#pragma unroll
                    for (int p = 0; p < 8; p++) {
                        uint64_t a = ap[dx + p];
                        acc[p][0] = fma2(wab.x, a, acc[p][0]);
                        acc[p][1] = fma2(wab.y, a, acc[p][1]);
                        acc[p][2] = fma2(wcd.x, a, acc[p][2]);
                        acc[p][3] = fma2(wcd.y, a, acc[p][3]);
                    }
                }
            }
        }
        __syncthreads();
    }

    // epilogue: bias + relu + gated combine over 8 experts, single store
    const int pp = ((r >> 3) << 1) + q;   // patch within tile
    float gv[8], bias[8];
#pragma unroll
    for (int e = 0; e < 8; e++) {
        gv[e] = g_s[pp][e];
        bias[e] = eb[e * 64 + bc];
    }

    float o[8];
#pragma unroll
    for (int p = 0; p < 8; p++) {
        float s = 0.f;
#pragma unroll
        for (int ep = 0; ep < 4; ep++) {
            float ylo, yhi;
            unpack2(acc[p][ep], ylo, yhi);
            int e0 = 2 * ep, e1 = 2 * ep + 1;
            s += gv[e0] * fmaxf(ylo + bias[e0], 0.f);
            s += gv[e1] * fmaxf(yhi + bias[e1], 0.f);
        }
        o[p] = s;
    }
    float* op = out + (((long)(b * 64 + bc) * 128 + y0 + r) * 128 + x0 + q * 8);
    reinterpret_cast<float4*>(op)[0] = make_float4(o[0], o[1], o[2], o[3]);
    reinterpret_cast<float4*>(op)[1] = make_float4(o[4], o[5], o[6], o[7]);
}

extern "C" void kernel_launch(void* const* d_in, const int* in_sizes, int n_in,
                              void* d_out, int out_size) {
    const float* x  = (const float*)d_in[0];   // [16,64,128,128]
    const float* ew = (const float*)d_in[1];   // [8,64,64,3,3]
    const float* eb = (const float*)d_in[2];   // [8,64]
    const float* gw = (const float*)d_in[3];   // [8,6144]
    const float* gb = (const float*)d_in[4];   // [8]
    float* out = (float*)d_out;                // [16,64,128,128]

    gate_kernel<<<4096, 256>>>(x, gw, gb);

    dim3 grid(64, 8, 16);  // (spatial tile, oc group of 8, batch)
    conv_kernel<<<grid, 256>>>(x, ew, eb, out);
}

// round 8
// speedup vs baseline: 1.1450x; 1.0019x over previous
#include <cuda_runtime.h>
#include <cstdint>

#define PI_F 3.14159265358979323846f

// gate scratch: [b][ph][pw][e] = [16][16][16][8]
__device__ float g_gate[16 * 16 * 16 * 8];

__device__ __forceinline__ uint64_t pack2(float a) {
    uint64_t r;
    asm("mov.b64 %0, {%1, %1};" : "=l"(r) : "r"(__float_as_uint(a)));
    return r;
}
__device__ __forceinline__ uint64_t fma2(uint64_t a, uint64_t b, uint64_t c) {
    uint64_t d;
    asm("fma.rn.f32x2 %0, %1, %2, %3;" : "=l"(d) : "l"(a), "l"(b), "l"(c));
    return d;
}
__device__ __forceinline__ void unpack2(uint64_t v, float& lo, float& hi) {
    uint32_t l, h;
    asm("mov.b64 {%0, %1}, %2;" : "=r"(l), "=r"(h) : "l"(v));
    lo = __uint_as_float(l);
    hi = __uint_as_float(h);
}

// ---------------------------------------------------------------------------
// Kernel 1: per-patch gating. One block (256 thr) per patch (B*16*16 = 4096).
// ---------------------------------------------------------------------------
__global__ void gate_kernel(const float* __restrict__ x,
                            const float* __restrict__ gate_w,
                            const float* __restrict__ gate_b) {
    const int blk = blockIdx.x;          // 0..4095
    const int b = blk >> 8;
    const int ph = (blk >> 4) & 15;
    const int pw = blk & 15;
    const int tid = threadIdx.x;

    float part[8];
#pragma unroll
    for (int e = 0; e < 8; e++) part[e] = 0.f;

    const float* xb = x + ((long)b * 64 * 128 + ph * 8) * 128 + pw * 8;

    for (int f = tid; f < 6144; f += 256) {
        int c = f >> 6;
        int r = f & 63;
        float v;
        if (c < 64) {
            int py = r >> 3, px = r & 7;
            v = xb[(c * 128 + py) * 128 + px];
        } else {
            int cc = c - 64;
            int grp = cc >> 3, k = cc & 7;
            float coord = (grp < 2) ? (ph + 0.5f) * (1.f / 16.f)
                                    : (pw + 0.5f) * (1.f / 16.f);
            float ang = coord * ((float)(1 << k) * PI_F);
            v = (grp & 1) ? cosf(ang) : sinf(ang);
        }
#pragma unroll
        for (int e = 0; e < 8; e++) part[e] += v * gate_w[e * 6144 + f];
    }

#pragma unroll
    for (int off = 16; off; off >>= 1) {
#pragma unroll
        for (int e = 0; e < 8; e++)
            part[e] += __shfl_down_sync(0xffffffffu, part[e], off);
    }

    __shared__ float s_red[8][8];
    __shared__ float s_logit[8];
    const int warp = tid >> 5, lane = tid & 31;
    if (lane == 0) {
#pragma unroll
        for (int e = 0; e < 8; e++) s_red[warp][e] = part[e];
    }
    __syncthreads();
    if (tid < 8) {
        float s = gate_b[tid];
#pragma unroll
        for (int w = 0; w < 8; w++) s += s_red[w][tid];
        s_logit[tid] = s;
    }
    __syncthreads();
    if (tid < 8) {
        float m = s_logit[0];
#pragma unroll
        for (int e = 1; e < 8; e++) m = fmaxf(m, s_logit[e]);
        float den = 0.f;
#pragma unroll
        for (int e = 0; e < 8; e++) den += expf(s_logit[e] - m);
        g_gate[blk * 8 + tid] = expf(s_logit[tid] - m) / den;
    }
}

// ---------------------------------------------------------------------------
// Kernel 2: fused 8-expert conv3x3 + bias + relu + gated combine.
// Block: batch b, 16x16 pixel tile, 8 base output channels x 8 experts
// (M = 64 conv channels). 256 threads: warp = base channel bl (weights are
// warp-uniform -> LDS.128 broadcast), lane -> (row r = lane>>1, half q =
// lane&1). Thread tile: 8 pixels (row r, cols 8q..8q+7) x 8 experts =
// 64 fp32 accs as 32 f32x2 pairs (pair = 2 adjacent experts).
// K chunked by 8 channels through static SMEM. Epilogue combines experts
// in-register -> each output element stored exactly once.
// ---------------------------------------------------------------------------
__global__ void __launch_bounds__(256, 2)
conv_kernel(const float* __restrict__ x,
            const float* __restrict__ ew,   // [8][64][64][3][3]
            const float* __restrict__ eb,   // [8][64]
            float* __restrict__ out) {
    __shared__ __align__(16) float in_s[8 * 324];       // [cl][18*18]
    __shared__ __align__(16) float w_s[8 * 9 * 64];     // [cl][tap][bl*8+e]
    __shared__ float g_s[4][8];                         // [patch-in-tile][e]

    const int tid = threadIdx.x;
    const int tileid = blockIdx.x;       // 0..63
    const int tx = tileid & 7, ty = tileid >> 3;
    const int grp = blockIdx.y;          // base channels grp*8 .. grp*8+7
    const int b = blockIdx.z;

    if (tid < 32) {
        int pp = tid >> 3, e = tid & 7;
        int ph = ty * 2 + (pp >> 1), pw = tx * 2 + (pp & 1);
        g_s[pp][e] = g_gate[((b * 16 + ph) * 16 + pw) * 8 + e];
    }

    const int bl = tid >> 5;             // 0..7 : base channel (== warp id)
    const int lane = tid & 31;
    const int r = lane >> 1;             // pixel row 0..15
    const int q = lane & 1;              // half: cols 8q..8q+7

    const int y0 = ty * 16, x0 = tx * 16;
    const int bc = grp * 8 + bl;

    uint64_t acc[8][4];                  // [pixel][expert-pair]
#pragma unroll
    for (int p = 0; p < 8; p++)
#pragma unroll
        for (int ep = 0; ep < 4; ep++) acc[p][ep] = 0ull;

    const float* xb = x + (long)b * 64 * 128 * 128;

    for (int c0 = 0; c0 < 64; c0 += 8) {
        // input tile: 8 channels x 18x18 (halo, zero-padded)
        for (int idx = tid; idx < 8 * 324; idx += 256) {
            int c = idx / 324;
            int rem = idx - c * 324;
            int iy = rem / 18;
            int ix = rem - iy * 18;
            int gy = y0 + iy - 1, gx = x0 + ix - 1;
            float v = 0.f;
            if ((unsigned)gy < 128u && (unsigned)gx < 128u)
                v = xb[((c0 + c) * 128 + gy) * 128 + gx];
            in_s[idx] = v;
        }
        // weights: w_s[cl][tap][m], m = blw*8 + e
        for (int idx = tid; idx < 8 * 9 * 64; idx += 256) {
            int cl = idx / 576;
            int rem = idx - cl * 576;
            int tap = rem >> 6;
            int m = rem & 63;
            int blw = m >> 3, e = m & 7;
            w_s[idx] = ew[((e * 64 + grp * 8 + blw) * 64 + c0 + cl) * 9 + tap];
        }
        __syncthreads();

#pragma unroll 1
        for (int cl = 0; cl < 8; cl++) {
            const float2* abase = reinterpret_cast<const float2*>(
                in_s + cl * 324 + r * 18 + q * 8);
            const float* wbase = w_s + cl * 576 + bl * 8;
#pragma unroll
            for (int dy = 0; dy < 3; dy++) {
                float2 v0 = abase[dy * 9 + 0];
                float2 v1 = abase[dy * 9 + 1];
                float2 v2 = abase[dy * 9 + 2];
                float2 v3 = abase[dy * 9 + 3];
                float2 v4 = abase[dy * 9 + 4];
                uint64_t ap[10];
                ap[0] = pack2(v0.x); ap[1] = pack2(v0.y);
                ap[2] = pack2(v1.x); ap[3] = pack2(v1.y);
                ap[4] = pack2(v2.x); ap[5] = pack2(v2.y);
                ap[6] = pack2(v3.x); ap[7] = pack2(v3.y);
                ap[8] = pack2(v4.x); ap[9] = pack2(v4.y);
#pragma unroll
                for (int dx = 0; dx < 3; dx++) {
                    const ulonglong2* wq =
                        reinterpret_cast<const ulonglong2*>(
                            wbase + (dy * 3 + dx) * 64);
                    ulonglong2 wab = wq[0];   // expert pairs 0,1 (LDS.128)
                    ulonglong2 wcd = wq[1];   // expert pairs 2,3 (LDS.128)
#pragma unroll
                    for (int p = 0; p < 8; p++) {
                        uint64_t a = ap[dx + p];
                        acc[p][0] = fma2(wab.x, a, acc[p][0]);
                        acc[p][1] = fma2(wab.y, a, acc[p][1]);
                        acc[p][2] = fma2(wcd.x, a, acc[p][2]);
                        acc[p][3] = fma2(wcd.y, a, acc[p][3]);
                    }
                }
            }
        }
        __syncthreads();
    }

    // epilogue: bias + relu + gated combine over 8 experts, single store
    const int pp = ((r >> 3) << 1) + q;   // patch within tile
    float gv[8], bias[8];
#pragma unroll
    for (int e = 0; e < 8; e++) {
        gv[e] = g_s[pp][e];
        bias[e] = eb[e * 64 + bc];
    }

    float o[8];
#pragma unroll
    for (int p = 0; p < 8; p++) {
        float s = 0.f;
#pragma unroll
        for (int ep = 0; ep < 4; ep++) {
            float ylo, yhi;
            unpack2(acc[p][ep], ylo, yhi);
            int e0 = 2 * ep, e1 = 2 * ep + 1;
            s += gv[e0] * fmaxf(ylo + bias[e0], 0.f);
            s += gv[e1] * fmaxf(yhi + bias[e1], 0.f);
        }
        o[p] = s;
    }
    float* op = out + (((long)(b * 64 + bc) * 128 + y0 + r) * 128 + x0 + q * 8);
    reinterpret_cast<float4*>(op)[0] = make_float4(o[0], o[1], o[2], o[3]);
    reinterpret_cast<float4*>(op)[1] = make_float4(o[4], o[5], o[6], o[7]);
}

extern "C" void kernel_launch(void* const* d_in, const int* in_sizes, int n_in,
                              void* d_out, int out_size) {
    const float* x  = (const float*)d_in[0];   // [16,64,128,128]
    const float* ew = (const float*)d_in[1];   // [8,64,64,3,3]
    const float* eb = (const float*)d_in[2];   // [8,64]
    const float* gw = (const float*)d_in[3];   // [8,6144]
    const float* gb = (const float*)d_in[4];   // [8]
    float* out = (float*)d_out;                // [16,64,128,128]

    gate_kernel<<<4096, 256>>>(x, gw, gb);

    dim3 grid(64, 8, 16);  // (spatial tile, oc group of 8, batch)
    conv_kernel<<<grid, 256>>>(x, ew, eb, out);
}

// round 9
// speedup vs baseline: 1.1454x; 1.0004x over previous
#include <cuda_runtime.h>
#include <cstdint>

#define PI_F 3.14159265358979323846f

// gate scratch: [b][ph][pw][e] = [16][16][16][8]
__device__ float g_gate[16 * 16 * 16 * 8];

__device__ __forceinline__ uint64_t pack2(float a) {
    uint64_t r;
    asm("mov.b64 %0, {%1, %1};" : "=l"(r) : "r"(__float_as_uint(a)));
    return r;
}
__device__ __forceinline__ uint64_t fma2(uint64_t a, uint64_t b, uint64_t c) {
    uint64_t d;
    asm("fma.rn.f32x2 %0, %1, %2, %3;" : "=l"(d) : "l"(a), "l"(b), "l"(c));
    return d;
}
__device__ __forceinline__ void unpack2(uint64_t v, float& lo, float& hi) {
    uint32_t l, h;
    asm("mov.b64 {%0, %1}, %2;" : "=r"(l), "=r"(h) : "l"(v));
    lo = __uint_as_float(l);
    hi = __uint_as_float(h);
}

// ---------------------------------------------------------------------------
// Kernel 1: per-patch gating. One block (256 thr) per patch (B*16*16 = 4096).
// ---------------------------------------------------------------------------
__global__ void gate_kernel(const float* __restrict__ x,
                            const float* __restrict__ gate_w,
                            const float* __restrict__ gate_b) {
    const int blk = blockIdx.x;          // 0..4095
    const int b = blk >> 8;
    const int ph = (blk >> 4) & 15;
    const int pw = blk & 15;
    const int tid = threadIdx.x;

    float part[8];
#pragma unroll
    for (int e = 0; e < 8; e++) part[e] = 0.f;

    const float* xb = x + ((long)b * 64 * 128 + ph * 8) * 128 + pw * 8;

    for (int f = tid; f < 6144; f += 256) {
        int c = f >> 6;
        int r = f & 63;
        float v;
        if (c < 64) {
            int py = r >> 3, px = r & 7;
            v = xb[(c * 128 + py) * 128 + px];
        } else {
            int cc = c - 64;
            int grp = cc >> 3, k = cc & 7;
            float coord = (grp < 2) ? (ph + 0.5f) * (1.f / 16.f)
                                    : (pw + 0.5f) * (1.f / 16.f);
            float ang = coord * ((float)(1 << k) * PI_F);
            v = (grp & 1) ? cosf(ang) : sinf(ang);
        }
#pragma unroll
        for (int e = 0; e < 8; e++) part[e] += v * gate_w[e * 6144 + f];
    }

#pragma unroll
    for (int off = 16; off; off >>= 1) {
#pragma unroll
        for (int e = 0; e < 8; e++)
            part[e] += __shfl_down_sync(0xffffffffu, part[e], off);
    }

    __shared__ float s_red[8][8];
    __shared__ float s_logit[8];
    const int warp = tid >> 5, lane = tid & 31;
    if (lane == 0) {
#pragma unroll
        for (int e = 0; e < 8; e++) s_red[warp][e] = part[e];
    }
    __syncthreads();
    if (tid < 8) {
        float s = gate_b[tid];
#pragma unroll
        for (int w = 0; w < 8; w++) s += s_red[w][tid];
        s_logit[tid] = s;
    }
    __syncthreads();
    if (tid < 8) {
        float m = s_logit[0];
#pragma unroll
        for (int e = 1; e < 8; e++) m = fmaxf(m, s_logit[e]);
        float den = 0.f;
#pragma unroll
        for (int e = 0; e < 8; e++) den += expf(s_logit[e] - m);
        g_gate[blk * 8 + tid] = expf(s_logit[tid] - m) / den;
    }
}

// ---------------------------------------------------------------------------
// Kernel 2: fused 8-expert conv3x3 + bias + relu + gated combine.
// Block: batch b, 16x16 pixel tile, 8 base output channels x 8 experts
// (M = 64 conv channels). 256 threads: warp = base channel bl (weights are
// warp-uniform -> LDS.128 broadcast), lane -> (row r = lane>>1, half q =
// lane&1). Thread tile: 8 pixels (row r, cols 8q..8q+7) x 8 experts =
// 64 fp32 accs as 32 f32x2 pairs (pair = 2 adjacent experts).
// K chunked by 8 channels through static SMEM. Epilogue combines experts
// in-register -> each output element stored exactly once.
// ---------------------------------------------------------------------------
__global__ void __launch_bounds__(256, 2)
conv_kernel(const float* __restrict__ x,
            const float* __restrict__ ew,   // [8][64][64][3][3]
            const float* __restrict__ eb,   // [8][64]
            float* __restrict__ out) {
    __shared__ __align__(16) float in_s[8 * 324];       // [cl][18*18]
    __shared__ __align__(16) float w_s[8 * 9 * 64];     // [cl][tap][bl*8+e]
    __shared__ float g_s[4][8];                         // [patch-in-tile][e]

    const int tid = threadIdx.x;
    const int tileid = blockIdx.x;       // 0..63
    const int tx = tileid & 7, ty = tileid >> 3;
    const int grp = blockIdx.y;          // base channels grp*8 .. grp*8+7
    const int b = blockIdx.z;

    if (tid < 32) {
        int pp = tid >> 3, e = tid & 7;
        int ph = ty * 2 + (pp >> 1), pw = tx * 2 + (pp & 1);
        g_s[pp][e] = g_gate[((b * 16 + ph) * 16 + pw) * 8 + e];
    }

    const int bl = tid >> 5;             // 0..7 : base channel (== warp id)
    const int lane = tid & 31;
    const int r = lane >> 1;             // pixel row 0..15
    const int q = lane & 1;              // half: cols 8q..8q+7

    const int y0 = ty * 16, x0 = tx * 16;
    const int bc = grp * 8 + bl;

    uint64_t acc[8][4];                  // [pixel][expert-pair]
#pragma unroll
    for (int p = 0; p < 8; p++)
#pragma unroll
        for (int ep = 0; ep < 4; ep++) acc[p][ep] = 0ull;

    const float* xb = x + (long)b * 64 * 128 * 128;

    for (int c0 = 0; c0 < 64; c0 += 8) {
        // input tile: 8 channels x 18x18 (halo, zero-padded)
        for (int idx = tid; idx < 8 * 324; idx += 256) {
            int c = idx / 324;
            int rem = idx - c * 324;
            int iy = rem / 18;
            int ix = rem - iy * 18;
            int gy = y0 + iy - 1, gx = x0 + ix - 1;
            float v = 0.f;
            if ((unsigned)gy < 128u && (unsigned)gx < 128u)
                v = xb[((c0 + c) * 128 + gy) * 128 + gx];
            in_s[idx] = v;
        }
        // weights: w_s[cl][tap][m], m = blw*8 + e
        for (int idx = tid; idx < 8 * 9 * 64; idx += 256) {
            int cl = idx / 576;
            int rem = idx - cl * 576;
            int tap = rem >> 6;
            int m = rem & 63;
            int blw = m >> 3, e = m & 7;
            w_s[idx] = ew[((e * 64 + grp * 8 + blw) * 64 + c0 + cl) * 9 + tap];
        }
        __syncthreads();

#pragma unroll 1
        for (int cl = 0; cl < 8; cl++) {
            const float2* abase = reinterpret_cast<const float2*>(
                in_s + cl * 324 + r * 18 + q * 8);
            const float* wbase = w_s + cl * 576 + bl * 8;
#pragma unroll
            for (int dy = 0; dy < 3; dy++) {
                float2 v0 = abase[dy * 9 + 0];
                float2 v1 = abase[dy * 9 + 1];
                float2 v2 = abase[dy * 9 + 2];
                float2 v3 = abase[dy * 9 + 3];
                float2 v4 = abase[dy * 9 + 4];
                uint64_t ap[10];
                ap[0] = pack2(v0.x); ap[1] = pack2(v0.y);
                ap[2] = pack2(v1.x); ap[3] = pack2(v1.y);
                ap[4] = pack2(v2.x); ap[5] = pack2(v2.y);
                ap[6] = pack2(v3.x); ap[7] = pack2(v3.y);
                ap[8] = pack2(v4.x); ap[9] = pack2(v4.y);
#pragma unroll
                for (int dx = 0; dx < 3; dx++) {
                    const ulonglong2* wq =
                        reinterpret_cast<const ulonglong2*>(
                            wbase + (dy * 3 + dx) * 64);
                    ulonglong2 wab = wq[0];   // expert pairs 0,1 (LDS.128)
                    ulonglong2 wcd = wq[1];   // expert pairs 2,3 (LDS.128)
#pragma unroll
                    for (int p = 0; p < 8; p++) {
                        uint64_t a = ap[dx + p];
                        acc[p][0] = fma2(wab.x, a, acc[p][0]);
                        acc[p][1] = fma2(wab.y, a, acc[p][1]);
                        acc[p][2] = fma2(wcd.x, a, acc[p][2]);
                        acc[p][3] = fma2(wcd.y, a, acc[p][3]);
                    }
                }
            }
        }
        __syncthreads();
    }

    // epilogue: bias + relu + gated combine over 8 experts, single store
    const int pp = ((r >> 3) << 1) + q;   // patch within tile
    float gv[8], bias[8];
#pragma unroll
    for (int e = 0; e < 8; e++) {
        gv[e] = g_s[pp][e];
        bias[e] = eb[e * 64 + bc];
    }

    float o[8];
#pragma unroll
    for (int p = 0; p < 8; p++) {
        float s = 0.f;
#pragma unroll
        for (int ep = 0; ep < 4; ep++) {
            float ylo, yhi;
            unpack2(acc[p][ep], ylo, yhi);
            int e0 = 2 * ep, e1 = 2 * ep + 1;
            s += gv[e0] * fmaxf(ylo + bias[e0], 0.f);
            s += gv[e1] * fmaxf(yhi + bias[e1], 0.f);
        }
        o[p] = s;
    }
    float* op = out + (((long)(b * 64 + bc) * 128 + y0 + r) * 128 + x0 + q * 8);
    reinterpret_cast<float4*>(op)[0] = make_float4(o[0], o[1], o[2], o[3]);
    reinterpret_cast<float4*>(op)[1] = make_float4(o[4], o[5], o[6], o[7]);
}

extern "C" void kernel_launch(void* const* d_in, const int* in_sizes, int n_in,
                              void* d_out, int out_size) {
    const float* x  = (const float*)d_in[0];   // [16,64,128,128]
    const float* ew = (const float*)d_in[1];   // [8,64,64,3,3]
    const float* eb = (const float*)d_in[2];   // [8,64]
    const float* gw = (const float*)d_in[3];   // [8,6144]
    const float* gb = (const float*)d_in[4];   // [8]
    float* out = (float*)d_out;                // [16,64,128,128]

    gate_kernel<<<4096, 256>>>(x, gw, gb);

    dim3 grid(64, 8, 16);  // (spatial tile, oc group of 8, batch)
    conv_kernel<<<grid, 256>>>(x, ew, eb, out);
}